// round 1
// baseline (speedup 1.0000x reference)
#include <cuda_runtime.h>

// Problem constants
#define BB 2
#define CC 128
#define HH 128
#define WW 256
#define KK 20
#define HW (HH * WW)
#define EPSV 1e-12f

// Scratch (no allocations allowed in kernel_launch)
__device__ float g_invn[BB * HH * CC];  // [b][h][c] : 1/max(||features[b,c,h,:]||, eps)
__device__ float g_pnT[CC * KK];        // [c][k]    : normalized prototypes, transposed
__device__ float g_pn2[KK];             // sum_c pn[k][c]^2

typedef unsigned long long u64;

__device__ __forceinline__ u64 pk2(float lo, float hi) {
    u64 r; asm("mov.b64 %0, {%1,%2};" : "=l"(r) : "f"(lo), "f"(hi)); return r;
}
__device__ __forceinline__ void upk2(u64 v, float& lo, float& hi) {
    asm("mov.b64 {%0,%1}, %2;" : "=f"(lo), "=f"(hi) : "l"(v));
}
__device__ __forceinline__ u64 fma2_(u64 a, u64 b, u64 c) {
    u64 d; asm("fma.rn.f32x2 %0, %1, %2, %3;" : "=l"(d) : "l"(a), "l"(b), "l"(c)); return d;
}
__device__ __forceinline__ u64 mul2_(u64 a, u64 b) {
    u64 d; asm("mul.rn.f32x2 %0, %1, %2;" : "=l"(d) : "l"(a), "l"(b)); return d;
}

__device__ __forceinline__ float wred(float v) {
#pragma unroll
    for (int o = 16; o > 0; o >>= 1) v += __shfl_xor_sync(0xffffffffu, v, o);
    return v;
}

// Kernel 1: per-(b,c,h) L2 norms over W (contiguous, coalesced float4 loads).
// One warp per row; writes inv-norm transposed to [b][h][c] for the main kernel.
__global__ void norms_kernel(const float* __restrict__ f) {
    int warp = (blockIdx.x * blockDim.x + threadIdx.x) >> 5;
    int lane = threadIdx.x & 31;
    int rid = warp;                       // rid = (b*C + c)*H + h, rid < B*C*H
    int h = rid % HH;
    int bc = rid / HH;
    int c = bc % CC;
    int b = bc / CC;
    const float4* r4 = (const float4*)(f + (size_t)rid * WW);
    float4 a = r4[lane];
    float4 bv = r4[lane + 32];
    float s = a.x * a.x + a.y * a.y + a.z * a.z + a.w * a.w
            + bv.x * bv.x + bv.y * bv.y + bv.z * bv.z + bv.w * bv.w;
    s = wred(s);
    if (lane == 0) {
        float inv = 1.0f / fmaxf(sqrtf(s), EPSV);
        g_invn[(b * HH + h) * CC + c] = inv;
    }
}

// Kernel 2: normalize prototypes. One warp per prototype (K=20 warps, 640 threads).
__global__ void proto_kernel(const float* __restrict__ p) {
    int warp = threadIdx.x >> 5;
    int lane = threadIdx.x & 31;
    if (warp >= KK) return;
    const float4* r4 = (const float4*)(p + warp * CC);
    float4 a = r4[lane];                  // 32 lanes * 4 = 128 = C
    float s = a.x * a.x + a.y * a.y + a.z * a.z + a.w * a.w;
    s = wred(s);
    float inv = 1.0f / fmaxf(sqrtf(s), EPSV);
    int cb = lane * 4;
    g_pnT[(cb + 0) * KK + warp] = a.x * inv;
    g_pnT[(cb + 1) * KK + warp] = a.y * inv;
    g_pnT[(cb + 2) * KK + warp] = a.z * inv;
    g_pnT[(cb + 3) * KK + warp] = a.w * inv;
    if (lane == 0) g_pn2[warp] = s * inv * inv;
}

// Kernel 3: main. Block = (b,h); 128 threads, each owns 2 adjacent w pixels packed
// into f32x2. dist^2 = ||fn||^2 + ||pn||^2 - 2 fn.pn with 21 packed-FMA accumulators.
__global__ __launch_bounds__(128) void main_kernel(const float* __restrict__ f,
                                                   const float* __restrict__ ds,
                                                   float* __restrict__ out) {
    __shared__ u64 s_pn[CC * KK];   // [c][k], prototype value duplicated in both lanes
    __shared__ u64 s_r[CC];         // inv-norm duplicated in both lanes
    __shared__ float s_pn2[KK];

    int tid = threadIdx.x;
    int b = blockIdx.x / HH;
    int h = blockIdx.x % HH;

    for (int i = tid; i < CC * KK; i += 128) {
        float v = g_pnT[i];
        s_pn[i] = pk2(v, v);
    }
    for (int i = tid; i < CC; i += 128) {
        float r = g_invn[(b * HH + h) * CC + i];
        s_r[i] = pk2(r, r);
    }
    if (tid < KK) s_pn2[tid] = g_pn2[tid];
    __syncthreads();

    const float* fb = f + (size_t)b * CC * HW + (size_t)h * WW + 2 * tid;

    u64 acc[KK];
#pragma unroll
    for (int k = 0; k < KK; k++) acc[k] = 0ull;   // bits 0 == (0.0f, 0.0f)
    u64 s2 = 0ull;

#pragma unroll 4
    for (int c = 0; c < CC; c++) {
        float2 xv = *(const float2*)(fb + (size_t)c * HW);
        u64 x = pk2(xv.x, xv.y);
        u64 fn = mul2_(x, s_r[c]);
        s2 = fma2_(fn, fn, s2);
        const u64* prow = &s_pn[c * KK];
#pragma unroll
        for (int k = 0; k < KK; k++) acc[k] = fma2_(fn, prow[k], acc[k]);
    }

    float s20, s21;
    upk2(s2, s20, s21);
    float scale = fabsf(ds[0]);
    float* ob = out + (size_t)b * KK * HW + (size_t)h * WW + 2 * tid;

#pragma unroll
    for (int k = 0; k < KK; k++) {
        float d0, d1;
        upk2(acc[k], d0, d1);
        float q = s_pn2[k];
        float v0 = fmaxf(s20 + q - 2.0f * d0, 0.0f);
        float v1 = fmaxf(s21 + q - 2.0f * d1, 0.0f);
        float2 o;
        o.x = -scale * sqrtf(v0);
        o.y = -scale * sqrtf(v1);
        *(float2*)(ob + (size_t)k * HW) = o;
    }
}

extern "C" void kernel_launch(void* const* d_in, const int* in_sizes, int n_in,
                              void* d_out, int out_size) {
    const float* features  = (const float*)d_in[0];
    const float* prototypes = (const float*)d_in[1];
    const float* dscale    = (const float*)d_in[2];
    float* out = (float*)d_out;

    // 1) row norms over W: B*C*H = 32768 rows, 1 warp each, 8 warps/block
    norms_kernel<<<(BB * CC * HH) / 8, 256>>>(features);
    // 2) prototype normalization
    proto_kernel<<<1, 640>>>(prototypes);
    // 3) distances + output
    main_kernel<<<BB * HH, 128>>>(features, dscale, out);
}

// round 2
// speedup vs baseline: 1.3678x; 1.3678x over previous
#include <cuda_runtime.h>

// Problem constants
#define BB 2
#define CC 128
#define HH 128
#define WW 256
#define KK 20
#define HW (HH * WW)
#define EPSV 1e-12f

// Scratch (no allocations allowed)
__device__ float g_invn[BB * HH * CC];  // [b][h][c] : 1/max(||features[b,c,h,:]||_W, eps)
__device__ float g_pnT[CC * KK];        // [c][k]    : normalized prototypes, transposed
__device__ float g_pn2[KK];             // ||pn_k||^2

typedef unsigned long long u64;

__device__ __forceinline__ u64 pk2(float lo, float hi) {
    u64 r; asm("mov.b64 %0, {%1,%2};" : "=l"(r) : "f"(lo), "f"(hi)); return r;
}
__device__ __forceinline__ void upk2(u64 v, float& lo, float& hi) {
    asm("mov.b64 {%0,%1}, %2;" : "=f"(lo), "=f"(hi) : "l"(v));
}
__device__ __forceinline__ u64 fma2_(u64 a, u64 b, u64 c) {
    u64 d; asm("fma.rn.f32x2 %0, %1, %2, %3;" : "=l"(d) : "l"(a), "l"(b), "l"(c)); return d;
}
__device__ __forceinline__ u64 mul2_(u64 a, u64 b) {
    u64 d; asm("mul.rn.f32x2 %0, %1, %2;" : "=l"(d) : "l"(a), "l"(b)); return d;
}

__device__ __forceinline__ float wred(float v) {
#pragma unroll
    for (int o = 16; o > 0; o >>= 1) v += __shfl_xor_sync(0xffffffffu, v, o);
    return v;
}
__device__ __forceinline__ float dot4(float4 a) {
    return a.x * a.x + a.y * a.y + a.z * a.z + a.w * a.w;
}

// Kernel 1: per-(b,c,h) L2 inv-norms over W. One warp handles 2 rows (4 LDG.128
// in flight per thread), 16384 warps total for latency hiding.
__global__ __launch_bounds__(256) void norms_kernel(const float* __restrict__ f) {
    int warp = (blockIdx.x * blockDim.x + threadIdx.x) >> 5;   // 0..16383
    int lane = threadIdx.x & 31;
    int r0 = warp * 2;                                          // rows r0, r0+1 (< 32768)
    const float4* a = (const float4*)(f + (size_t)r0 * WW);
    float4 p0 = a[lane];
    float4 p1 = a[lane + 32];
    float4 p2 = a[lane + 64];
    float4 p3 = a[lane + 96];
    float sA = wred(dot4(p0) + dot4(p1));
    float sB = wred(dot4(p2) + dot4(p3));
    if (lane == 0) {
        // row rid -> (b, c, h); store transposed at [b][h][c]
        int h0 = r0 % HH;
        int bc = r0 / HH;
        int c = bc % CC;
        int b = bc / CC;
        g_invn[(b * HH + h0) * CC + c]       = 1.0f / fmaxf(sqrtf(sA), EPSV);
        g_invn[(b * HH + h0 + 1) * CC + c]   = 1.0f / fmaxf(sqrtf(sB), EPSV);
    }
}

// Kernel 2: normalize prototypes (tiny). One warp per prototype.
__global__ void proto_kernel(const float* __restrict__ p) {
    int warp = threadIdx.x >> 5;
    int lane = threadIdx.x & 31;
    if (warp >= KK) return;
    const float4* r4 = (const float4*)(p + warp * CC);
    float4 a = r4[lane];
    float s = wred(dot4(a));
    float inv = 1.0f / fmaxf(sqrtf(s), EPSV);
    int cb = lane * 4;
    g_pnT[(cb + 0) * KK + warp] = a.x * inv;
    g_pnT[(cb + 1) * KK + warp] = a.y * inv;
    g_pnT[(cb + 2) * KK + warp] = a.z * inv;
    g_pnT[(cb + 3) * KK + warp] = a.w * inv;
    if (lane == 0) g_pn2[warp] = s * inv * inv;
}

// Main-loop body, templated on whether this warp also accumulates ||fn||^2.
template <bool KG0>
__device__ __forceinline__ void dot_loop(const float4* __restrict__ fp,
                                         const u64* __restrict__ s_pn_k,
                                         const u64* __restrict__ s_r2,
                                         u64 acc[2][5], u64 s2[2]) {
#pragma unroll 4
    for (int c = 0; c < CC; c++) {
        float4 xv = fp[(size_t)c * (HW / 4)];
        u64 x0 = pk2(xv.x, xv.y);
        u64 x1 = pk2(xv.z, xv.w);
        const u64* pr = s_pn_k + c * KK;
#pragma unroll
        for (int j = 0; j < 5; j++) {
            acc[0][j] = fma2_(x0, pr[j], acc[0][j]);
            acc[1][j] = fma2_(x1, pr[j], acc[1][j]);
        }
        if (KG0) {
            u64 r2 = s_r2[c];
            s2[0] = fma2_(mul2_(x0, r2), x0, s2[0]);
            s2[1] = fma2_(mul2_(x1, r2), x1, s2[1]);
        }
    }
}

// Kernel 3: main. Block = (b,h), 256 threads.
// Thread t: pxg = t%64 -> pixels w = 4*pxg..4*pxg+3 ; kg = t/64 -> k = 5*kg..5*kg+4.
// dot(fn, p_k) = sum_c x_c * (r_c * p_kc) with r folded into SMEM prototypes once.
__global__ __launch_bounds__(256) void main_kernel(const float* __restrict__ f,
                                                   const float* __restrict__ ds,
                                                   float* __restrict__ out) {
    __shared__ u64 s_pn[CC * KK];   // [c][k] : r_c * p_kc, dup-packed
    __shared__ u64 s_r2[CC];        // r_c^2, dup-packed
    __shared__ u64 s_s2[2 * 64];    // per pixel-pair ||fn||^2 (packed)
    __shared__ float s_pn2[KK];

    int tid = threadIdx.x;
    int b = blockIdx.x / HH;
    int h = blockIdx.x % HH;
    int pxg = tid & 63;
    int kg = tid >> 6;

    const float* invn = g_invn + (size_t)(b * HH + h) * CC;
    for (int i = tid; i < CC * KK; i += 256) {
        float v = g_pnT[i] * invn[i / KK];
        s_pn[i] = pk2(v, v);
    }
    if (tid < CC) {
        float r = invn[tid];
        float r2 = r * r;
        s_r2[tid] = pk2(r2, r2);
    }
    if (tid < KK) s_pn2[tid] = g_pn2[tid];
    __syncthreads();

    const float4* fp = (const float4*)f + ((size_t)b * CC * HW + (size_t)h * WW) / 4 + pxg;

    u64 acc[2][5];
#pragma unroll
    for (int j = 0; j < 5; j++) { acc[0][j] = 0ull; acc[1][j] = 0ull; }
    u64 s2[2] = {0ull, 0ull};

    if (kg == 0) dot_loop<true>(fp, s_pn + kg * 5, s_r2, acc, s2);
    else         dot_loop<false>(fp, s_pn + kg * 5, s_r2, acc, s2);

    if (kg == 0) {
        s_s2[2 * pxg]     = s2[0];
        s_s2[2 * pxg + 1] = s2[1];
    }
    __syncthreads();

    float n0, n1, n2, n3;
    upk2(s_s2[2 * pxg], n0, n1);
    upk2(s_s2[2 * pxg + 1], n2, n3);

    float scale = fabsf(ds[0]);
    float* ob = out + (size_t)b * KK * HW + (size_t)h * WW + 4 * pxg;

#pragma unroll
    for (int j = 0; j < 5; j++) {
        int k = kg * 5 + j;
        float q = s_pn2[k];
        float d0, d1, d2, d3;
        upk2(acc[0][j], d0, d1);
        upk2(acc[1][j], d2, d3);
        float4 o;
        o.x = -scale * sqrtf(fmaxf(n0 + q - 2.0f * d0, 0.0f));
        o.y = -scale * sqrtf(fmaxf(n1 + q - 2.0f * d1, 0.0f));
        o.z = -scale * sqrtf(fmaxf(n2 + q - 2.0f * d2, 0.0f));
        o.w = -scale * sqrtf(fmaxf(n3 + q - 2.0f * d3, 0.0f));
        *(float4*)(ob + (size_t)k * HW) = o;
    }
}

extern "C" void kernel_launch(void* const* d_in, const int* in_sizes, int n_in,
                              void* d_out, int out_size) {
    const float* features   = (const float*)d_in[0];
    const float* prototypes = (const float*)d_in[1];
    const float* dscale     = (const float*)d_in[2];
    float* out = (float*)d_out;

    // 1) inv-norms over W: 32768 rows, 2 rows/warp, 16384 warps
    norms_kernel<<<2048, 256>>>(features);
    // 2) prototype normalization
    proto_kernel<<<1, 640>>>(prototypes);
    // 3) distances + output
    main_kernel<<<BB * HH, 256>>>(features, dscale, out);
}

// round 3
// speedup vs baseline: 1.6590x; 1.2129x over previous
#include <cuda_runtime.h>

// Problem constants
#define BB 2
#define CC 128
#define HH 128
#define WW 256
#define KK 20
#define HW (HH * WW)
#define EPSV 1e-12f

typedef unsigned long long u64;

__device__ __forceinline__ u64 pk2(float lo, float hi) {
    u64 r; asm("mov.b64 %0, {%1,%2};" : "=l"(r) : "f"(lo), "f"(hi)); return r;
}
__device__ __forceinline__ void upk2(u64 v, float& lo, float& hi) {
    asm("mov.b64 {%0,%1}, %2;" : "=f"(lo), "=f"(hi) : "l"(v));
}
__device__ __forceinline__ u64 fma2_(u64 a, u64 b, u64 c) {
    u64 d; asm("fma.rn.f32x2 %0, %1, %2, %3;" : "=l"(d) : "l"(a), "l"(b), "l"(c)); return d;
}
__device__ __forceinline__ u64 mul2_(u64 a, u64 b) {
    u64 d; asm("mul.rn.f32x2 %0, %1, %2;" : "=l"(d) : "l"(a), "l"(b)); return d;
}
__device__ __forceinline__ u64 add2_(u64 a, u64 b) {
    u64 d; asm("add.rn.f32x2 %0, %1, %2;" : "=l"(d) : "l"(a), "l"(b)); return d;
}
__device__ __forceinline__ float wred(float v) {
#pragma unroll
    for (int o = 16; o > 0; o >>= 1) v += __shfl_xor_sync(0xffffffffu, v, o);
    return v;
}
__device__ __forceinline__ float dot4(float4 a) {
    return a.x * a.x + a.y * a.y + a.z * a.z + a.w * a.w;
}

// Templated inner dot loop over one 64-c half. KG0 warps also accumulate ||fn||^2.
template <bool KG0>
__device__ __forceinline__ void dot_loop(const float4* __restrict__ fp,
                                         const u64* __restrict__ pbase,   // s_pn + c0*KK + kg*5
                                         const u64* __restrict__ r2base,  // s_r2 + c0
                                         u64 acc[2][5], u64 s2[2]) {
#pragma unroll 4
    for (int cc = 0; cc < 64; cc++) {
        float4 xv = fp[(size_t)cc * (HW / 4)];
        u64 x0 = pk2(xv.x, xv.y);
        u64 x1 = pk2(xv.z, xv.w);
        const u64* pr = pbase + cc * KK;
#pragma unroll
        for (int j = 0; j < 5; j++) {
            acc[0][j] = fma2_(x0, pr[j], acc[0][j]);
            acc[1][j] = fma2_(x1, pr[j], acc[1][j]);
        }
        if (KG0) {
            u64 r2 = r2base[cc];
            s2[0] = fma2_(mul2_(x0, r2), x0, s2[0]);
            s2[1] = fma2_(mul2_(x1, r2), x1, s2[1]);
        }
    }
}

// Single fused kernel. Block = (b,h), 512 threads.
// tid = pxg (bits 0-5, 64 groups x 4 px) | kg (bits 6-7, 4 groups x 5 k) | ch (bit 8, c-half).
__global__ __launch_bounds__(512, 2) void iso_kernel(const float* __restrict__ f,
                                                     const float* __restrict__ p,
                                                     const float* __restrict__ ds,
                                                     float* __restrict__ out) {
    __shared__ u64 s_pn[CC * KK];    // [c][k] : inv_c * pinv_k * p[k][c], dup-packed (20 KB)
    __shared__ u64 s_red[256 * 10];  // cross-ch partial-dot exchange (20 KB)
    __shared__ u64 s_r2[CC];         // inv_c^2, dup-packed
    __shared__ u64 s_s2h[64 * 2];    // ch1 partial ||fn||^2
    __shared__ u64 s_s2[64 * 2];     // final ||fn||^2 per pixel pair
    __shared__ float s_inv[CC];
    __shared__ float s_pinv[KK];
    __shared__ float s_pn2[KK];

    int tid = threadIdx.x;
    int w = tid >> 5, lane = tid & 31;
    int b = blockIdx.x / HH, h = blockIdx.x % HH;
    const float* fbh = f + (size_t)b * CC * HW + (size_t)h * WW;

    // ---- Pass 1a: feature W-norms. Warp w handles c = w + 16j; 4-row batches for MLP.
#pragma unroll
    for (int jb = 0; jb < 2; jb++) {
        float4 v[8];
        int cbase = w + jb * 64;
#pragma unroll
        for (int j = 0; j < 4; j++) {
            const float4* r4 = (const float4*)(fbh + (size_t)(cbase + 16 * j) * HW);
            v[2 * j]     = r4[lane];
            v[2 * j + 1] = r4[lane + 32];
        }
#pragma unroll
        for (int j = 0; j < 4; j++) {
            float s = wred(dot4(v[2 * j]) + dot4(v[2 * j + 1]));
            if (lane == 0) {
                int c = cbase + 16 * j;
                float r = 1.0f / fmaxf(sqrtf(s), EPSV);
                s_inv[c] = r;
                s_r2[c] = pk2(r * r, r * r);
            }
        }
    }
    // ---- Pass 1b: prototype norms (warp w handles k = w, w+16)
    for (int k = w; k < KK; k += 16) {
        float4 a = ((const float4*)(p + k * CC))[lane];
        float s = wred(dot4(a));
        if (lane == 0) {
            float inv = 1.0f / fmaxf(sqrtf(s), EPSV);
            s_pinv[k] = inv;
            s_pn2[k] = s * inv * inv;
        }
    }
    __syncthreads();

    // ---- Fill folded prototype table: s_pn[c][k] = p[k][c] * pinv_k * inv_c
    for (int i = tid; i < CC * KK; i += 512) {
        int c = i / KK, k = i - c * KK;
        float val = __ldg(p + k * CC + c) * s_pinv[k] * s_inv[c];
        s_pn[i] = pk2(val, val);
    }
    __syncthreads();

    // ---- Main dot loop
    int pxg = tid & 63;
    int kg = (tid >> 6) & 3;
    int ch = tid >> 8;
    int c0 = ch * 64;

    const float4* fp = (const float4*)(fbh + (size_t)c0 * HW) + pxg;
    const u64* pbase = s_pn + c0 * KK + kg * 5;
    const u64* r2base = s_r2 + c0;

    u64 acc[2][5];
#pragma unroll
    for (int j = 0; j < 5; j++) { acc[0][j] = 0ull; acc[1][j] = 0ull; }
    u64 s2[2] = {0ull, 0ull};

    if (kg == 0) dot_loop<true>(fp, pbase, r2base, acc, s2);
    else         dot_loop<false>(fp, pbase, r2base, acc, s2);

    // ---- Cross-ch reduction
    if (ch == 1) {
        int base = (tid & 255) * 10;
#pragma unroll
        for (int i = 0; i < 2; i++)
#pragma unroll
            for (int j = 0; j < 5; j++) s_red[base + i * 5 + j] = acc[i][j];
        if (kg == 0) { s_s2h[2 * pxg] = s2[0]; s_s2h[2 * pxg + 1] = s2[1]; }
    }
    __syncthreads();
    if (ch == 0) {
        int base = tid * 10;
#pragma unroll
        for (int i = 0; i < 2; i++)
#pragma unroll
            for (int j = 0; j < 5; j++) acc[i][j] = add2_(acc[i][j], s_red[base + i * 5 + j]);
        if (kg == 0) {
            s2[0] = add2_(s2[0], s_s2h[2 * pxg]);
            s2[1] = add2_(s2[1], s_s2h[2 * pxg + 1]);
            s_s2[2 * pxg] = s2[0];
            s_s2[2 * pxg + 1] = s2[1];
        }
    }
    __syncthreads();

    // ---- Epilogue: ch0 threads write 5 k-planes x 4 px
    if (ch == 0) {
        float n0, n1, n2, n3;
        upk2(s_s2[2 * pxg], n0, n1);
        upk2(s_s2[2 * pxg + 1], n2, n3);
        float scale = fabsf(ds[0]);
        float* ob = out + ((size_t)b * KK * HH + h) * WW + 4 * pxg;
#pragma unroll
        for (int j = 0; j < 5; j++) {
            int k = kg * 5 + j;
            float q = s_pn2[k];
            float d0, d1, d2, d3;
            upk2(acc[0][j], d0, d1);
            upk2(acc[1][j], d2, d3);
            float4 o;
            o.x = -scale * sqrtf(fmaxf(n0 + q - 2.0f * d0, 0.0f));
            o.y = -scale * sqrtf(fmaxf(n1 + q - 2.0f * d1, 0.0f));
            o.z = -scale * sqrtf(fmaxf(n2 + q - 2.0f * d2, 0.0f));
            o.w = -scale * sqrtf(fmaxf(n3 + q - 2.0f * d3, 0.0f));
            *(float4*)(ob + (size_t)k * HW) = o;
        }
    }
}

extern "C" void kernel_launch(void* const* d_in, const int* in_sizes, int n_in,
                              void* d_out, int out_size) {
    const float* features   = (const float*)d_in[0];
    const float* prototypes = (const float*)d_in[1];
    const float* dscale     = (const float*)d_in[2];
    float* out = (float*)d_out;

    iso_kernel<<<BB * HH, 512>>>(features, prototypes, dscale, out);
}